// round 15
// baseline (speedup 1.0000x reference)
#include <cuda_runtime.h>
#include <cstdint>

// Problem constants
#define C_  8
#define N_  16384
#define D_  1024
#define DQ_ 128
#define K_  128
#define ESPLIT 16
#define NTILES (N_ / 64 * C_)   // 2048 tiles of 64 rows
#define SGRID  444              // 148 SMs x 3 resident blocks

static __device__ __constant__ float INV_SQRT_DQ = 0.08838834764831845f; // 1/sqrt(128)
static __device__ __constant__ float INV_SQRT_D  = 0.03125f;             // 1/sqrt(1024)

// Scratch (static device globals — no allocation)
__device__ float g_s[C_ * N_];
__device__ float g_w[C_ * D_];
__device__ int   g_topidx[C_ * K_];
__device__ float g_Aw[C_ * K_];
__device__ float g_g[C_ * D_];
__device__ float g_part[ESPLIT * C_ * D_];
__device__ float g_gp[C_ * 32 * D_];     // per-block partial g (32 slots/cluster)
__device__ int   g_cntA[C_ * 2];         // gather reduction counters per (c, half)
__device__ int   g_cntB[C_];             // fpart reduction counters (zero-init)

// ---------------------------------------------------------------------------
// Per cluster: qk[j] = key_c · Wq[:,j] + bq[j], then w[d] = Wq[d,:] · qk.
__global__ void __launch_bounds__(1024) k_prep(const float* __restrict__ key,
                                               const float* __restrict__ Wq,
                                               const float* __restrict__ bq) {
    int c = blockIdx.x, tid = threadIdx.x;
    int warp = tid >> 5, lane = tid & 31;
    __shared__ float sk[D_];
    __shared__ float spart[32 * DQ_];
    __shared__ float sqk[DQ_];

    sk[tid] = key[(size_t)c * D_ + tid];
    __syncthreads();
    {
        float a0 = 0.f, a1 = 0.f, a2 = 0.f, a3 = 0.f;
        const float4* wq4 = (const float4*)Wq;
#pragma unroll 4
        for (int r = 0; r < 32; ++r) {
            int d = warp * 32 + r;
            float kd = sk[d];
            float4 f = wq4[(size_t)d * 32 + lane];
            a0 += kd * f.x; a1 += kd * f.y; a2 += kd * f.z; a3 += kd * f.w;
        }
        spart[warp * DQ_ + lane * 4 + 0] = a0;
        spart[warp * DQ_ + lane * 4 + 1] = a1;
        spart[warp * DQ_ + lane * 4 + 2] = a2;
        spart[warp * DQ_ + lane * 4 + 3] = a3;
    }
    __syncthreads();
    if (tid < DQ_) {
        float s = bq[tid];
#pragma unroll 8
        for (int w = 0; w < 32; ++w) s += spart[w * DQ_ + tid];
        sqk[tid] = s;
    }
    __syncthreads();
    {
        const float4* row = (const float4*)(Wq + (size_t)tid * DQ_);
        const float4* q4 = (const float4*)sqk;
        float acc = 0.f;
#pragma unroll
        for (int j = 0; j < DQ_ / 4; ++j) {
            float4 a = row[j], b = q4[j];
            acc += a.x * b.x + a.y * b.y + a.z * b.z + a.w * b.w;
        }
        g_w[c * D_ + tid] = acc;
    }
}

// ---------------------------------------------------------------------------
// s[c,n] = feats[c,n,:] · w_c — persistent grid-stride, proven shape (frozen).
__global__ void __launch_bounds__(256, 3) k_scores(const float* __restrict__ feats) {
    int warp = threadIdx.x >> 5, lane = threadIdx.x & 31;
    for (int tile = blockIdx.x; tile < NTILES; tile += SGRID) {
        int c = tile >> 8;                 // 256 tiles per cluster
        int row0 = (tile & 255) * 64 + warp * 8;
        const float4* base = (const float4*)(feats + (size_t)c * N_ * D_)
                             + (size_t)row0 * (D_ / 4) + lane;
        const float4* wv4 = (const float4*)(g_w + c * D_);

        float a0 = 0.f, a1 = 0.f, a2 = 0.f, a3 = 0.f;
        float a4 = 0.f, a5 = 0.f, a6 = 0.f, a7 = 0.f;
#pragma unroll
        for (int k = 0; k < 8; ++k) {
            float4 w  = __ldg(wv4 + lane + 32 * k);
            float4 f0 = __ldcs(base +    0 + 32 * k);
            float4 f1 = __ldcs(base +  256 + 32 * k);
            float4 f2 = __ldcs(base +  512 + 32 * k);
            float4 f3 = __ldcs(base +  768 + 32 * k);
            float4 f4 = __ldcs(base + 1024 + 32 * k);
            float4 f5 = __ldcs(base + 1280 + 32 * k);
            float4 f6 = __ldcs(base + 1536 + 32 * k);
            float4 f7 = __ldcs(base + 1792 + 32 * k);
            a0 += f0.x * w.x + f0.y * w.y + f0.z * w.z + f0.w * w.w;
            a1 += f1.x * w.x + f1.y * w.y + f1.z * w.z + f1.w * w.w;
            a2 += f2.x * w.x + f2.y * w.y + f2.z * w.z + f2.w * w.w;
            a3 += f3.x * w.x + f3.y * w.y + f3.z * w.z + f3.w * w.w;
            a4 += f4.x * w.x + f4.y * w.y + f4.z * w.z + f4.w * w.w;
            a5 += f5.x * w.x + f5.y * w.y + f5.z * w.z + f5.w * w.w;
            a6 += f6.x * w.x + f6.y * w.y + f6.z * w.z + f6.w * w.w;
            a7 += f7.x * w.x + f7.y * w.y + f7.z * w.z + f7.w * w.w;
        }
#pragma unroll
        for (int o = 16; o; o >>= 1) {
            a0 += __shfl_xor_sync(0xFFFFFFFFu, a0, o);
            a1 += __shfl_xor_sync(0xFFFFFFFFu, a1, o);
            a2 += __shfl_xor_sync(0xFFFFFFFFu, a2, o);
            a3 += __shfl_xor_sync(0xFFFFFFFFu, a3, o);
            a4 += __shfl_xor_sync(0xFFFFFFFFu, a4, o);
            a5 += __shfl_xor_sync(0xFFFFFFFFu, a5, o);
            a6 += __shfl_xor_sync(0xFFFFFFFFu, a6, o);
            a7 += __shfl_xor_sync(0xFFFFFFFFu, a7, o);
        }
        if (lane == 0) {
            float* sp = g_s + c * N_ + row0;
            sp[0] = a0; sp[1] = a1; sp[2] = a2; sp[3] = a3;
            sp[4] = a4; sp[5] = a5; sp[6] = a6; sp[7] = a7;
        }
    }
}

// ---------------------------------------------------------------------------
// Order-preserving float<->uint transforms
__device__ __forceinline__ unsigned flip_f(float v) {
    unsigned b = __float_as_uint(v);
    return (b & 0x80000000u) ? ~b : (b | 0x80000000u);
}
__device__ __forceinline__ float unflip_f(unsigned u) {
    unsigned b = (u & 0x80000000u) ? (u ^ 0x80000000u) : ~u;
    return __uint_as_float(b);
}

// Parallel radix-digit select (warp 0, lane owns 8 digits, shfl suffix-scan).
__device__ __forceinline__ void digit_select(const unsigned* hist, int kneed,
                                             int* sh_digit, int* sh_rem,
                                             int tid) {
    if (tid < 32) {
        unsigned h[8];
        unsigned loc = 0;
#pragma unroll
        for (int i = 0; i < 8; ++i) { h[i] = hist[tid * 8 + i]; loc += h[i]; }
        unsigned suf = loc;
#pragma unroll
        for (int off = 1; off < 32; off <<= 1) {
            unsigned v = __shfl_down_sync(0xFFFFFFFFu, suf, off);
            if (tid + off < 32) suf += v;
        }
        unsigned sexcl = suf - loc;
        if ((int)sexcl < kneed && kneed <= (int)suf) {
            int run = kneed - (int)sexcl;
#pragma unroll
            for (int i = 7; i >= 0; --i) {
                unsigned hh = h[i];
                if ((int)hh >= run) { *sh_digit = tid * 8 + i; *sh_rem = run; break; }
                run -= (int)hh;
            }
        }
    }
}

// One block per cluster. No max pass (scores are tiny; softmax shift-invariant).
// Fused Z+histogram pass, parallel digit select, exact top-K with stable
// tie-break, sorted descending, second softmax A_.
__global__ void __launch_bounds__(1024) k_topk() {
    __shared__ unsigned hist[256];
    __shared__ int tie[1024];
    __shared__ unsigned selU[K_];
    __shared__ int selI[K_];
    __shared__ unsigned long long skey[K_];
    __shared__ float sp[K_];
    __shared__ float red2[K_];
    __shared__ float red[32];
    __shared__ float sZ_s;
    __shared__ int sh_digit, sh_rem, cnt, tcnt;

    int c = blockIdx.x, tid = threadIdx.x;
    const float4* s4 = (const float4*)(g_s + c * N_);

    if (tid < 256) hist[tid] = 0;
    __syncthreads();

    float myz = 0.f;
#pragma unroll
    for (int r = 0; r < 4; ++r) {
        float4 v = s4[tid + 1024 * r];
        myz += __expf(v.x * INV_SQRT_DQ) + __expf(v.y * INV_SQRT_DQ)
             + __expf(v.z * INV_SQRT_DQ) + __expf(v.w * INV_SQRT_DQ);
        atomicAdd(&hist[flip_f(v.x) >> 24], 1u);
        atomicAdd(&hist[flip_f(v.y) >> 24], 1u);
        atomicAdd(&hist[flip_f(v.z) >> 24], 1u);
        atomicAdd(&hist[flip_f(v.w) >> 24], 1u);
    }
    for (int o = 16; o; o >>= 1) myz += __shfl_xor_sync(~0u, myz, o);
    if ((tid & 31) == 0) red[tid >> 5] = myz;
    __syncthreads();
    if (tid < 32) {
        float v = red[tid];
        for (int o = 16; o; o >>= 1) v += __shfl_xor_sync(~0u, v, o);
        if (tid == 0) sZ_s = v;
    }
    __syncthreads();
    float Z = sZ_s;

    digit_select(hist, K_, &sh_digit, &sh_rem, tid);
    __syncthreads();
    unsigned prefix = ((unsigned)sh_digit) << 24;
    int kneed = sh_rem;
    __syncthreads();

    for (int shift = 16; shift >= 0; shift -= 8) {
        if (tid < 256) hist[tid] = 0;
        __syncthreads();
        unsigned mask = 0xFFFFFFFFu << (shift + 8);
#pragma unroll
        for (int r = 0; r < 4; ++r) {
            float4 v = s4[tid + 1024 * r];
            unsigned u;
            u = flip_f(v.x); if ((u & mask) == prefix) atomicAdd(&hist[(u >> shift) & 255], 1u);
            u = flip_f(v.y); if ((u & mask) == prefix) atomicAdd(&hist[(u >> shift) & 255], 1u);
            u = flip_f(v.z); if ((u & mask) == prefix) atomicAdd(&hist[(u >> shift) & 255], 1u);
            u = flip_f(v.w); if ((u & mask) == prefix) atomicAdd(&hist[(u >> shift) & 255], 1u);
        }
        __syncthreads();
        digit_select(hist, kneed, &sh_digit, &sh_rem, tid);
        __syncthreads();
        prefix |= ((unsigned)sh_digit) << shift;
        kneed = sh_rem;
        __syncthreads();
    }
    unsigned T = prefix;

    if (tid == 0) { cnt = 0; tcnt = 0; }
    __syncthreads();
#pragma unroll
    for (int r = 0; r < 4; ++r) {
        float4 v = s4[tid + 1024 * r];
        float vs[4] = {v.x, v.y, v.z, v.w};
#pragma unroll
        for (int e = 0; e < 4; ++e) {
            unsigned u = flip_f(vs[e]);
            int i = (tid + 1024 * r) * 4 + e;
            if (u > T) {
                int p = atomicAdd(&cnt, 1);
                selU[p] = u; selI[p] = i;
            } else if (u == T) {
                int p = atomicAdd(&tcnt, 1);
                if (p < 1024) tie[p] = i;
            }
        }
    }
    __syncthreads();
    int m = cnt;
    if (tid == 0) {
        int tn = tcnt < 1024 ? tcnt : 1024;
        for (int r = 0; r < kneed; ++r) {
            int best = 0x7FFFFFFF, bi = 0;
            for (int t = 0; t < tn; ++t)
                if (tie[t] < best) { best = tie[t]; bi = t; }
            tie[bi] = 0x7FFFFFFF;
            selU[m + r] = T; selI[m + r] = best;
        }
    }
    __syncthreads();

    if (tid < K_)
        skey[tid] = ((unsigned long long)selU[tid] << 32) | (unsigned)(~selI[tid]);
    __syncthreads();
    for (int size = 2; size <= K_; size <<= 1) {
        for (int stride = size >> 1; stride > 0; stride >>= 1) {
            if (tid < K_) {
                int j = tid ^ stride;
                if (j > tid) {
                    bool asc = ((tid & size) == 0);
                    unsigned long long a = skey[tid], b = skey[j];
                    if ((a < b) == asc) { skey[tid] = b; skey[j] = a; }
                }
            }
            __syncthreads();
        }
    }

    if (tid < K_) {
        unsigned long long kk = skey[tid];
        unsigned u = (unsigned)(kk >> 32);
        int idx = (int)(~(unsigned)kk);
        float v = unflip_f(u);
        sp[tid] = __expf(v * INV_SQRT_DQ) / Z;
        g_topidx[c * K_ + tid] = idx;
    }
    __syncthreads();
    float p0 = sp[0];
    float e = 0.f;
    if (tid < K_) { e = __expf((sp[tid] - p0) * INV_SQRT_D); red2[tid] = e; }
    __syncthreads();
    for (int s2 = 64; s2 > 0; s2 >>= 1) {
        if (tid < s2) red2[tid] += red2[tid + s2];
        __syncthreads();
    }
    if (tid < K_) g_Aw[c * K_ + tid] = e / red2[0];
}

// ---------------------------------------------------------------------------
// Gather + fused g, split along D: block (g, h) copies the d-half
// [h*512, h*512+512) of 4 selected rows, writes its half-partial to g_gp,
// and the last of the 32 blocks per (cluster, half) reduces the 32 half-
// partials in fixed ascending slot order into g_g. 512 blocks x 128 thr —
// 2x parallelism of R14 and half the per-block/tail critical path; identical
// summation order, so bitwise-equal g_g.
__global__ void __launch_bounds__(128) k_gather_g(const float* __restrict__ feats,
                                                  float* __restrict__ out) {
    __shared__ int isLast;
    int tid = threadIdx.x;                // 0..127
    int h = blockIdx.y;                   // d-half
    int col = h * 128 + tid;              // float4 column 0..255
    int r0 = blockIdx.x * 4;              // global selected row base
    int c = r0 >> 7, k0 = r0 & 127;
    int slot = k0 >> 2;                   // 0..31 within cluster
    const int* ip = g_topidx + c * K_ + k0;
    int i0 = ip[0], i1 = ip[1], i2 = ip[2], i3 = ip[3];
    const float* ap = g_Aw + c * K_ + k0;
    float A0 = ap[0], A1 = ap[1], A2 = ap[2], A3 = ap[3];
    const float4* fb = (const float4*)(feats + (size_t)c * N_ * D_);
    float4* ob = (float4*)(out + (size_t)r0 * D_);
    float4 v0 = __ldg(fb + (size_t)i0 * 256 + col);
    float4 v1 = __ldg(fb + (size_t)i1 * 256 + col);
    float4 v2 = __ldg(fb + (size_t)i2 * 256 + col);
    float4 v3 = __ldg(fb + (size_t)i3 * 256 + col);
    ob[col]       = v0;
    ob[256 + col] = v1;
    ob[512 + col] = v2;
    ob[768 + col] = v3;

    float4 p;
    p.x = A0 * v0.x + A1 * v1.x + A2 * v2.x + A3 * v3.x;
    p.y = A0 * v0.y + A1 * v1.y + A2 * v2.y + A3 * v3.y;
    p.z = A0 * v0.z + A1 * v1.z + A2 * v2.z + A3 * v3.z;
    p.w = A0 * v0.w + A1 * v1.w + A2 * v2.w + A3 * v3.w;
    ((float4*)(g_gp + ((size_t)c * 32 + slot) * D_))[col] = p;

    __syncthreads();
    if (tid == 0) {
        __threadfence();
        isLast = (atomicAdd(&g_cntA[c * 2 + h], 1) == 31);
    }
    __syncthreads();
    if (isLast) {
        __threadfence();
        float4 acc = make_float4(0.f, 0.f, 0.f, 0.f);
        const float4* gp = (const float4*)(g_gp + (size_t)c * 32 * D_);
#pragma unroll 8
        for (int s = 0; s < 32; ++s) {
            float4 q = gp[s * 256 + col];
            acc.x += q.x; acc.y += q.y; acc.z += q.z; acc.w += q.w;
        }
        ((float4*)(g_g + (size_t)c * D_))[col] = acc;
        if (tid == 0) g_cntA[c * 2 + h] = 0;
    }
}

// ---------------------------------------------------------------------------
// fusion partials + fused final (threadFenceReduction, ascending es order).
__global__ void __launch_bounds__(1024) k_fpart(const float* __restrict__ Wv,
                                                const float* __restrict__ bv,
                                                float* __restrict__ outf) {
    __shared__ int isLast;
    int es = blockIdx.x, c = blockIdx.y, d = threadIdx.x;
    const int EC = D_ / ESPLIT; // 64
    __shared__ float sg[EC];
    int e0 = es * EC;
    if (d < EC) sg[d] = g_g[c * D_ + e0 + d];
    __syncthreads();
    const float* wp = Wv + (size_t)e0 * D_ + d;
    float acc = 0.f;
#pragma unroll 8
    for (int e = 0; e < EC; ++e) acc += sg[e] * wp[(size_t)e * D_];
    g_part[(es * C_ + c) * D_ + d] = acc;

    __syncthreads();
    if (d == 0) {
        __threadfence();
        isLast = (atomicAdd(&g_cntB[c], 1) == ESPLIT - 1);
    }
    __syncthreads();
    if (isLast) {
        __threadfence();
        float a2 = bv[d];
#pragma unroll
        for (int e2 = 0; e2 < ESPLIT; ++e2) a2 += g_part[(e2 * C_ + c) * D_ + d];
        outf[c * D_ + d] = a2;
        if (d == 0) g_cntB[c] = 0;
    }
}

// ---------------------------------------------------------------------------
extern "C" void kernel_launch(void* const* d_in, const int* in_sizes, int n_in,
                              void* d_out, int out_size) {
    const float* feats = (const float*)d_in[0];  // [C, N, D]
    const float* key   = (const float*)d_in[1];  // [C, 1, D]
    const float* Wq    = (const float*)d_in[2];  // [D, DQ]
    const float* bq    = (const float*)d_in[3];  // [DQ]
    const float* Wv    = (const float*)d_in[4];  // [D, D]
    const float* bv    = (const float*)d_in[5];  // [D]
    float* out  = (float*)d_out;                  // selected_features [C*K, D]
    float* outf = out + (size_t)C_ * K_ * D_;     // fusion [C, D]

    k_prep<<<C_, 1024>>>(key, Wq, bq);
    k_scores<<<SGRID, 256>>>(feats);              // persistent, grid-stride
    k_topk<<<C_, 1024>>>();
    k_gather_g<<<dim3(C_ * K_ / 4, 2), 128>>>(feats, out);
    k_fpart<<<dim3(ESPLIT, C_), 1024>>>(Wv, bv, outf);
}

// round 16
// speedup vs baseline: 1.0491x; 1.0491x over previous
#include <cuda_runtime.h>
#include <cstdint>

// Problem constants
#define C_  8
#define N_  16384
#define D_  1024
#define DQ_ 128
#define K_  128
#define ESPLIT 16
#define NTILES (N_ / 64 * C_)   // 2048 tiles of 64 rows
#define SGRID  444              // 148 SMs x 3 resident blocks

static __device__ __constant__ float INV_SQRT_DQ = 0.08838834764831845f; // 1/sqrt(128)
static __device__ __constant__ float INV_SQRT_D  = 0.03125f;             // 1/sqrt(1024)

// Scratch (static device globals — no allocation)
__device__ float g_s[C_ * N_];
__device__ float g_w[C_ * D_];
__device__ int   g_topidx[C_ * K_];
__device__ float g_Aw[C_ * K_];
__device__ float g_part[ESPLIT * C_ * D_];
__device__ float g_gp[C_ * 32 * D_];     // per-block partial g (32 slots/cluster)
__device__ int   g_cntB[C_];             // fpart reduction counters (zero-init)

// ---------------------------------------------------------------------------
// Per cluster: qk[j] = key_c · Wq[:,j] + bq[j], then w[d] = Wq[d,:] · qk.
__global__ void __launch_bounds__(1024) k_prep(const float* __restrict__ key,
                                               const float* __restrict__ Wq,
                                               const float* __restrict__ bq) {
    int c = blockIdx.x, tid = threadIdx.x;
    int warp = tid >> 5, lane = tid & 31;
    __shared__ float sk[D_];
    __shared__ float spart[32 * DQ_];
    __shared__ float sqk[DQ_];

    sk[tid] = key[(size_t)c * D_ + tid];
    __syncthreads();
    {
        float a0 = 0.f, a1 = 0.f, a2 = 0.f, a3 = 0.f;
        const float4* wq4 = (const float4*)Wq;
#pragma unroll 4
        for (int r = 0; r < 32; ++r) {
            int d = warp * 32 + r;
            float kd = sk[d];
            float4 f = wq4[(size_t)d * 32 + lane];
            a0 += kd * f.x; a1 += kd * f.y; a2 += kd * f.z; a3 += kd * f.w;
        }
        spart[warp * DQ_ + lane * 4 + 0] = a0;
        spart[warp * DQ_ + lane * 4 + 1] = a1;
        spart[warp * DQ_ + lane * 4 + 2] = a2;
        spart[warp * DQ_ + lane * 4 + 3] = a3;
    }
    __syncthreads();
    if (tid < DQ_) {
        float s = bq[tid];
#pragma unroll 8
        for (int w = 0; w < 32; ++w) s += spart[w * DQ_ + tid];
        sqk[tid] = s;
    }
    __syncthreads();
    {
        const float4* row = (const float4*)(Wq + (size_t)tid * DQ_);
        const float4* q4 = (const float4*)sqk;
        float acc = 0.f;
#pragma unroll
        for (int j = 0; j < DQ_ / 4; ++j) {
            float4 a = row[j], b = q4[j];
            acc += a.x * b.x + a.y * b.y + a.z * b.z + a.w * b.w;
        }
        g_w[c * D_ + tid] = acc;
    }
}

// ---------------------------------------------------------------------------
// s[c,n] = feats[c,n,:] · w_c — persistent grid-stride, proven shape (frozen).
__global__ void __launch_bounds__(256, 3) k_scores(const float* __restrict__ feats) {
    int warp = threadIdx.x >> 5, lane = threadIdx.x & 31;
    for (int tile = blockIdx.x; tile < NTILES; tile += SGRID) {
        int c = tile >> 8;                 // 256 tiles per cluster
        int row0 = (tile & 255) * 64 + warp * 8;
        const float4* base = (const float4*)(feats + (size_t)c * N_ * D_)
                             + (size_t)row0 * (D_ / 4) + lane;
        const float4* wv4 = (const float4*)(g_w + c * D_);

        float a0 = 0.f, a1 = 0.f, a2 = 0.f, a3 = 0.f;
        float a4 = 0.f, a5 = 0.f, a6 = 0.f, a7 = 0.f;
#pragma unroll
        for (int k = 0; k < 8; ++k) {
            float4 w  = __ldg(wv4 + lane + 32 * k);
            float4 f0 = __ldcs(base +    0 + 32 * k);
            float4 f1 = __ldcs(base +  256 + 32 * k);
            float4 f2 = __ldcs(base +  512 + 32 * k);
            float4 f3 = __ldcs(base +  768 + 32 * k);
            float4 f4 = __ldcs(base + 1024 + 32 * k);
            float4 f5 = __ldcs(base + 1280 + 32 * k);
            float4 f6 = __ldcs(base + 1536 + 32 * k);
            float4 f7 = __ldcs(base + 1792 + 32 * k);
            a0 += f0.x * w.x + f0.y * w.y + f0.z * w.z + f0.w * w.w;
            a1 += f1.x * w.x + f1.y * w.y + f1.z * w.z + f1.w * w.w;
            a2 += f2.x * w.x + f2.y * w.y + f2.z * w.z + f2.w * w.w;
            a3 += f3.x * w.x + f3.y * w.y + f3.z * w.z + f3.w * w.w;
            a4 += f4.x * w.x + f4.y * w.y + f4.z * w.z + f4.w * w.w;
            a5 += f5.x * w.x + f5.y * w.y + f5.z * w.z + f5.w * w.w;
            a6 += f6.x * w.x + f6.y * w.y + f6.z * w.z + f6.w * w.w;
            a7 += f7.x * w.x + f7.y * w.y + f7.z * w.z + f7.w * w.w;
        }
#pragma unroll
        for (int o = 16; o; o >>= 1) {
            a0 += __shfl_xor_sync(0xFFFFFFFFu, a0, o);
            a1 += __shfl_xor_sync(0xFFFFFFFFu, a1, o);
            a2 += __shfl_xor_sync(0xFFFFFFFFu, a2, o);
            a3 += __shfl_xor_sync(0xFFFFFFFFu, a3, o);
            a4 += __shfl_xor_sync(0xFFFFFFFFu, a4, o);
            a5 += __shfl_xor_sync(0xFFFFFFFFu, a5, o);
            a6 += __shfl_xor_sync(0xFFFFFFFFu, a6, o);
            a7 += __shfl_xor_sync(0xFFFFFFFFu, a7, o);
        }
        if (lane == 0) {
            float* sp = g_s + c * N_ + row0;
            sp[0] = a0; sp[1] = a1; sp[2] = a2; sp[3] = a3;
            sp[4] = a4; sp[5] = a5; sp[6] = a6; sp[7] = a7;
        }
    }
}

// ---------------------------------------------------------------------------
// Order-preserving float<->uint transforms
__device__ __forceinline__ unsigned flip_f(float v) {
    unsigned b = __float_as_uint(v);
    return (b & 0x80000000u) ? ~b : (b | 0x80000000u);
}
__device__ __forceinline__ float unflip_f(unsigned u) {
    unsigned b = (u & 0x80000000u) ? (u ^ 0x80000000u) : ~u;
    return __uint_as_float(b);
}

// Parallel radix-digit select (warp 0, lane owns 8 digits, shfl suffix-scan).
__device__ __forceinline__ void digit_select(const unsigned* hist, int kneed,
                                             int* sh_digit, int* sh_rem,
                                             int tid) {
    if (tid < 32) {
        unsigned h[8];
        unsigned loc = 0;
#pragma unroll
        for (int i = 0; i < 8; ++i) { h[i] = hist[tid * 8 + i]; loc += h[i]; }
        unsigned suf = loc;
#pragma unroll
        for (int off = 1; off < 32; off <<= 1) {
            unsigned v = __shfl_down_sync(0xFFFFFFFFu, suf, off);
            if (tid + off < 32) suf += v;
        }
        unsigned sexcl = suf - loc;
        if ((int)sexcl < kneed && kneed <= (int)suf) {
            int run = kneed - (int)sexcl;
#pragma unroll
            for (int i = 7; i >= 0; --i) {
                unsigned hh = h[i];
                if ((int)hh >= run) { *sh_digit = tid * 8 + i; *sh_rem = run; break; }
                run -= (int)hh;
            }
        }
    }
}

// One block per cluster. No max pass (scores are tiny; softmax shift-invariant).
// Fused Z+histogram pass, parallel digit select, exact top-K with stable
// tie-break, sorted descending, second softmax A_.
__global__ void __launch_bounds__(1024) k_topk() {
    __shared__ unsigned hist[256];
    __shared__ int tie[1024];
    __shared__ unsigned selU[K_];
    __shared__ int selI[K_];
    __shared__ unsigned long long skey[K_];
    __shared__ float sp[K_];
    __shared__ float red2[K_];
    __shared__ float red[32];
    __shared__ float sZ_s;
    __shared__ int sh_digit, sh_rem, cnt, tcnt;

    int c = blockIdx.x, tid = threadIdx.x;
    const float4* s4 = (const float4*)(g_s + c * N_);

    if (tid < 256) hist[tid] = 0;
    __syncthreads();

    float myz = 0.f;
#pragma unroll
    for (int r = 0; r < 4; ++r) {
        float4 v = s4[tid + 1024 * r];
        myz += __expf(v.x * INV_SQRT_DQ) + __expf(v.y * INV_SQRT_DQ)
             + __expf(v.z * INV_SQRT_DQ) + __expf(v.w * INV_SQRT_DQ);
        atomicAdd(&hist[flip_f(v.x) >> 24], 1u);
        atomicAdd(&hist[flip_f(v.y) >> 24], 1u);
        atomicAdd(&hist[flip_f(v.z) >> 24], 1u);
        atomicAdd(&hist[flip_f(v.w) >> 24], 1u);
    }
    for (int o = 16; o; o >>= 1) myz += __shfl_xor_sync(~0u, myz, o);
    if ((tid & 31) == 0) red[tid >> 5] = myz;
    __syncthreads();
    if (tid < 32) {
        float v = red[tid];
        for (int o = 16; o; o >>= 1) v += __shfl_xor_sync(~0u, v, o);
        if (tid == 0) sZ_s = v;
    }
    __syncthreads();
    float Z = sZ_s;

    digit_select(hist, K_, &sh_digit, &sh_rem, tid);
    __syncthreads();
    unsigned prefix = ((unsigned)sh_digit) << 24;
    int kneed = sh_rem;
    __syncthreads();

    for (int shift = 16; shift >= 0; shift -= 8) {
        if (tid < 256) hist[tid] = 0;
        __syncthreads();
        unsigned mask = 0xFFFFFFFFu << (shift + 8);
#pragma unroll
        for (int r = 0; r < 4; ++r) {
            float4 v = s4[tid + 1024 * r];
            unsigned u;
            u = flip_f(v.x); if ((u & mask) == prefix) atomicAdd(&hist[(u >> shift) & 255], 1u);
            u = flip_f(v.y); if ((u & mask) == prefix) atomicAdd(&hist[(u >> shift) & 255], 1u);
            u = flip_f(v.z); if ((u & mask) == prefix) atomicAdd(&hist[(u >> shift) & 255], 1u);
            u = flip_f(v.w); if ((u & mask) == prefix) atomicAdd(&hist[(u >> shift) & 255], 1u);
        }
        __syncthreads();
        digit_select(hist, kneed, &sh_digit, &sh_rem, tid);
        __syncthreads();
        prefix |= ((unsigned)sh_digit) << shift;
        kneed = sh_rem;
        __syncthreads();
    }
    unsigned T = prefix;

    if (tid == 0) { cnt = 0; tcnt = 0; }
    __syncthreads();
#pragma unroll
    for (int r = 0; r < 4; ++r) {
        float4 v = s4[tid + 1024 * r];
        float vs[4] = {v.x, v.y, v.z, v.w};
#pragma unroll
        for (int e = 0; e < 4; ++e) {
            unsigned u = flip_f(vs[e]);
            int i = (tid + 1024 * r) * 4 + e;
            if (u > T) {
                int p = atomicAdd(&cnt, 1);
                selU[p] = u; selI[p] = i;
            } else if (u == T) {
                int p = atomicAdd(&tcnt, 1);
                if (p < 1024) tie[p] = i;
            }
        }
    }
    __syncthreads();
    int m = cnt;
    if (tid == 0) {
        int tn = tcnt < 1024 ? tcnt : 1024;
        for (int r = 0; r < kneed; ++r) {
            int best = 0x7FFFFFFF, bi = 0;
            for (int t = 0; t < tn; ++t)
                if (tie[t] < best) { best = tie[t]; bi = t; }
            tie[bi] = 0x7FFFFFFF;
            selU[m + r] = T; selI[m + r] = best;
        }
    }
    __syncthreads();

    if (tid < K_)
        skey[tid] = ((unsigned long long)selU[tid] << 32) | (unsigned)(~selI[tid]);
    __syncthreads();
    for (int size = 2; size <= K_; size <<= 1) {
        for (int stride = size >> 1; stride > 0; stride >>= 1) {
            if (tid < K_) {
                int j = tid ^ stride;
                if (j > tid) {
                    bool asc = ((tid & size) == 0);
                    unsigned long long a = skey[tid], b = skey[j];
                    if ((a < b) == asc) { skey[tid] = b; skey[j] = a; }
                }
            }
            __syncthreads();
        }
    }

    if (tid < K_) {
        unsigned long long kk = skey[tid];
        unsigned u = (unsigned)(kk >> 32);
        int idx = (int)(~(unsigned)kk);
        float v = unflip_f(u);
        sp[tid] = __expf(v * INV_SQRT_DQ) / Z;
        g_topidx[c * K_ + tid] = idx;
    }
    __syncthreads();
    float p0 = sp[0];
    float e = 0.f;
    if (tid < K_) { e = __expf((sp[tid] - p0) * INV_SQRT_D); red2[tid] = e; }
    __syncthreads();
    for (int s2 = 64; s2 > 0; s2 >>= 1) {
        if (tid < s2) red2[tid] += red2[tid + s2];
        __syncthreads();
    }
    if (tid < K_) g_Aw[c * K_ + tid] = e / red2[0];
}

// ---------------------------------------------------------------------------
// Gather + partial g (R14 shape, NO tail reduce): block copies 4 selected
// rows (in registers) to out and writes its A_-weighted partial into g_gp.
// The 32-slot reduction moved to k_fpart's prologue — kills the serial
// last-block tail that made R14's gather_g 9.4us.
__global__ void __launch_bounds__(256) k_gather_g(const float* __restrict__ feats,
                                                  float* __restrict__ out) {
    int tid = threadIdx.x;
    int r0 = blockIdx.x * 4;              // global selected row base
    int c = r0 >> 7, k0 = r0 & 127;
    int slot = k0 >> 2;                   // 0..31 within cluster
    const int* ip = g_topidx + c * K_ + k0;
    int i0 = ip[0], i1 = ip[1], i2 = ip[2], i3 = ip[3];
    const float* ap = g_Aw + c * K_ + k0;
    float A0 = ap[0], A1 = ap[1], A2 = ap[2], A3 = ap[3];
    const float4* fb = (const float4*)(feats + (size_t)c * N_ * D_);
    float4* ob = (float4*)(out + (size_t)r0 * D_);
    float4 v0 = __ldg(fb + (size_t)i0 * 256 + tid);
    float4 v1 = __ldg(fb + (size_t)i1 * 256 + tid);
    float4 v2 = __ldg(fb + (size_t)i2 * 256 + tid);
    float4 v3 = __ldg(fb + (size_t)i3 * 256 + tid);
    ob[tid]       = v0;
    ob[256 + tid] = v1;
    ob[512 + tid] = v2;
    ob[768 + tid] = v3;

    float4 p;
    p.x = A0 * v0.x + A1 * v1.x + A2 * v2.x + A3 * v3.x;
    p.y = A0 * v0.y + A1 * v1.y + A2 * v2.y + A3 * v3.y;
    p.z = A0 * v0.z + A1 * v1.z + A2 * v2.z + A3 * v3.z;
    p.w = A0 * v0.w + A1 * v1.w + A2 * v2.w + A3 * v3.w;
    ((float4*)(g_gp + ((size_t)c * 32 + slot) * D_))[tid] = p;
}

// ---------------------------------------------------------------------------
// fusion: block (es, c) first reduces the 32 g-partials for its own 64-elem
// e-chunk (ascending slot order — bitwise-identical g to R14), then computes
// its Wv partial; last of 16 blocks per cluster adds bias and writes outf.
__global__ void __launch_bounds__(1024) k_fpart(const float* __restrict__ Wv,
                                                const float* __restrict__ bv,
                                                float* __restrict__ outf) {
    __shared__ int isLast;
    int es = blockIdx.x, c = blockIdx.y, d = threadIdx.x;
    const int EC = D_ / ESPLIT; // 64
    __shared__ float sg[EC];
    int e0 = es * EC;
    if (d < EC) {
        const float* gp = g_gp + (size_t)c * 32 * D_ + e0 + d;
        float s = 0.f;
#pragma unroll
        for (int sl = 0; sl < 32; ++sl) s += gp[(size_t)sl * D_];
        sg[d] = s;
    }
    __syncthreads();
    const float* wp = Wv + (size_t)e0 * D_ + d;
    float acc = 0.f;
#pragma unroll 8
    for (int e = 0; e < EC; ++e) acc += sg[e] * wp[(size_t)e * D_];
    g_part[(es * C_ + c) * D_ + d] = acc;

    __syncthreads();
    if (d == 0) {
        __threadfence();
        isLast = (atomicAdd(&g_cntB[c], 1) == ESPLIT - 1);
    }
    __syncthreads();
    if (isLast) {
        __threadfence();
        float a2 = bv[d];
#pragma unroll
        for (int e2 = 0; e2 < ESPLIT; ++e2) a2 += g_part[(e2 * C_ + c) * D_ + d];
        outf[c * D_ + d] = a2;
        if (d == 0) g_cntB[c] = 0;
    }
}

// ---------------------------------------------------------------------------
extern "C" void kernel_launch(void* const* d_in, const int* in_sizes, int n_in,
                              void* d_out, int out_size) {
    const float* feats = (const float*)d_in[0];  // [C, N, D]
    const float* key   = (const float*)d_in[1];  // [C, 1, D]
    const float* Wq    = (const float*)d_in[2];  // [D, DQ]
    const float* bq    = (const float*)d_in[3];  // [DQ]
    const float* Wv    = (const float*)d_in[4];  // [D, D]
    const float* bv    = (const float*)d_in[5];  // [D]
    float* out  = (float*)d_out;                  // selected_features [C*K, D]
    float* outf = out + (size_t)C_ * K_ * D_;     // fusion [C, D]

    k_prep<<<C_, 1024>>>(key, Wq, bq);
    k_scores<<<SGRID, 256>>>(feats);              // persistent, grid-stride
    k_topk<<<C_, 1024>>>();
    k_gather_g<<<C_ * K_ / 4, 256>>>(feats, out);
    k_fpart<<<dim3(ESPLIT, C_), 1024>>>(Wv, bv, outf);
}